// round 5
// baseline (speedup 1.0000x reference)
#include <cuda_runtime.h>
#include <math.h>

#define SS 512
#define BB 64
#define II 256
#define HH 1024
#define BH (BB*HH)

// ============================================================================
// Kernel 1: xproj[s*B+b, h] = dot(x[s,b,:], Wx[h,:]) + bx[h]
// GEMM: M=32768, K=256, N=1024 (both operands K-major -> NT GEMM)
// Tile 64x64, Ktile 16, 256 threads, 4x4 register tile per thread.
// Writes directly into d_out's h_seq region (same shape).
// ============================================================================
__global__ __launch_bounds__(256) void xproj_kernel(
    const float* __restrict__ x, const float* __restrict__ Wx,
    const float* __restrict__ bx, float* __restrict__ out)
{
    __shared__ __align__(16) float xs[16][68];
    __shared__ __align__(16) float ws[16][68];
    const int mBase = blockIdx.y * 64;
    const int nBase = blockIdx.x * 64;
    const int tid = threadIdx.x;
    const int tx = tid & 15;        // n-thread (4 cols each)
    const int ty = tid >> 4;        // m-thread (4 rows each)
    const int r = tid >> 2;         // fill: row 0..63
    const int c = tid & 3;          // fill: float4 index 0..3

    float acc[4][4] = {};

    for (int k0 = 0; k0 < II; k0 += 16) {
        float4 xa = *(const float4*)&x [(size_t)(mBase + r) * II + k0 + c * 4];
        float4 wa = *(const float4*)&Wx[(size_t)(nBase + r) * II + k0 + c * 4];
        __syncthreads();
        xs[c*4+0][r] = xa.x; xs[c*4+1][r] = xa.y; xs[c*4+2][r] = xa.z; xs[c*4+3][r] = xa.w;
        ws[c*4+0][r] = wa.x; ws[c*4+1][r] = wa.y; ws[c*4+2][r] = wa.z; ws[c*4+3][r] = wa.w;
        __syncthreads();
        #pragma unroll
        for (int kk = 0; kk < 16; kk++) {
            float4 a = *(const float4*)&xs[kk][ty * 4];
            float4 b = *(const float4*)&ws[kk][tx * 4];
            acc[0][0] += a.x*b.x; acc[0][1] += a.x*b.y; acc[0][2] += a.x*b.z; acc[0][3] += a.x*b.w;
            acc[1][0] += a.y*b.x; acc[1][1] += a.y*b.y; acc[1][2] += a.y*b.z; acc[1][3] += a.y*b.w;
            acc[2][0] += a.z*b.x; acc[2][1] += a.z*b.y; acc[2][2] += a.z*b.z; acc[2][3] += a.z*b.w;
            acc[3][0] += a.w*b.x; acc[3][1] += a.w*b.y; acc[3][2] += a.w*b.z; acc[3][3] += a.w*b.w;
        }
    }

    #pragma unroll
    for (int i = 0; i < 4; i++) {
        #pragma unroll
        for (int j = 0; j < 4; j++) {
            int row = mBase + ty * 4 + i;
            int col = nBase + tx * 4 + j;
            out[(size_t)row * HH + col] = acc[i][j] + bx[col];
        }
    }
}

// ============================================================================
// Kernel 2: t=0 step. h0 = 0, so h_seq[0] = tanh(xproj[0] + bh). In place.
// ============================================================================
__global__ void step0_kernel(float* __restrict__ h, const float* __restrict__ bh)
{
    int idx = blockIdx.x * blockDim.x + threadIdx.x;
    h[idx] = tanhf(h[idx] + bh[idx & (HH - 1)]);
}

// ============================================================================
// Kernel 3 (x511): h_t[m, n] = tanh( sum_k h_prev[m,k] * Wh[n,k] + bh[n] + xproj_t[m,n] )
// Grid = 128 CTAs, each owns an 8-column slice of H (tile M=64, N=8).
// 256 threads = 16 m_thr x 2 n_thr x 8 k-split warps; 4x4 register tile each.
// Split-K partials reduced through shared memory, then bias+xproj+tanh,
// overwriting xproj_t in place (hx serves as input xproj and output h).
// Global loads are register-double-buffered (prefetch next K-chunk of 64).
// ============================================================================
__global__ __launch_bounds__(256) void step_kernel(
    const float* __restrict__ h_prev, const float* __restrict__ Wh,
    const float* __restrict__ bh, float* __restrict__ hx)
{
    __shared__ __align__(16) float hs[64][68];   // [k][m], padded
    __shared__ __align__(16) float ws[64][8];    // [k][n]
    __shared__ float red[8][512];                // split-K partials

    const int tid   = threadIdx.x;
    const int nBase = blockIdx.x * 8;
    const int ks    = tid >> 5;          // warp index = k-split group 0..7
    const int lane  = tid & 31;
    const int n_thr = lane & 1;          // 0..1 (4 n each)
    const int m_thr = lane >> 1;         // 0..15 (4 m each)

    float acc[4][4] = {};

    // prefetch chunk 0
    float4 ph[4];
    float  pw[2];
    #pragma unroll
    for (int j = 0; j < 4; j++) {
        int lin = tid + j * 256;
        int m = lin >> 4, f = lin & 15;
        ph[j] = *(const float4*)&h_prev[(size_t)m * HH + f * 4];
    }
    #pragma unroll
    for (int j = 0; j < 2; j++) {
        int lin = tid + j * 256;
        int n = lin >> 6, k = lin & 63;
        pw[j] = Wh[(size_t)(nBase + n) * HH + k];
    }

    for (int cblk = 0; cblk < HH / 64; cblk++) {
        __syncthreads();   // previous compute done with smem
        #pragma unroll
        for (int j = 0; j < 4; j++) {
            int lin = tid + j * 256;
            int m = lin >> 4, f = lin & 15;
            hs[f*4+0][m] = ph[j].x; hs[f*4+1][m] = ph[j].y;
            hs[f*4+2][m] = ph[j].z; hs[f*4+3][m] = ph[j].w;
        }
        #pragma unroll
        for (int j = 0; j < 2; j++) {
            int lin = tid + j * 256;
            int n = lin >> 6, k = lin & 63;
            ws[k][n] = pw[j];
        }
        __syncthreads();

        // prefetch next chunk while computing this one
        if (cblk + 1 < HH / 64) {
            int kNext = (cblk + 1) * 64;
            #pragma unroll
            for (int j = 0; j < 4; j++) {
                int lin = tid + j * 256;
                int m = lin >> 4, f = lin & 15;
                ph[j] = *(const float4*)&h_prev[(size_t)m * HH + kNext + f * 4];
            }
            #pragma unroll
            for (int j = 0; j < 2; j++) {
                int lin = tid + j * 256;
                int n = lin >> 6, k = lin & 63;
                pw[j] = Wh[(size_t)(nBase + n) * HH + kNext + k];
            }
        }

        #pragma unroll
        for (int kq = 0; kq < 8; kq++) {
            int k = ks * 8 + kq;
            float4 a = *(const float4*)&hs[k][m_thr * 4];
            float4 b = *(const float4*)&ws[k][n_thr * 4];
            acc[0][0] += a.x*b.x; acc[0][1] += a.x*b.y; acc[0][2] += a.x*b.z; acc[0][3] += a.x*b.w;
            acc[1][0] += a.y*b.x; acc[1][1] += a.y*b.y; acc[1][2] += a.y*b.z; acc[1][3] += a.y*b.w;
            acc[2][0] += a.z*b.x; acc[2][1] += a.z*b.y; acc[2][2] += a.z*b.z; acc[2][3] += a.z*b.w;
            acc[3][0] += a.w*b.x; acc[3][1] += a.w*b.y; acc[3][2] += a.w*b.z; acc[3][3] += a.w*b.w;
        }
    }

    // split-K reduction through shared memory
    __syncthreads();
    #pragma unroll
    for (int i = 0; i < 4; i++)
        #pragma unroll
        for (int j = 0; j < 4; j++)
            red[ks][(m_thr * 4 + i) * 8 + n_thr * 4 + j] = acc[i][j];
    __syncthreads();

    #pragma unroll
    for (int r2 = 0; r2 < 2; r2++) {
        int o = tid + r2 * 256;           // 0..511 = m*8 + n_local
        float s = 0.f;
        #pragma unroll
        for (int p = 0; p < 8; p++) s += red[p][o];
        int m = o >> 3;
        int n = (o & 7) + nBase;
        size_t idx = (size_t)m * HH + n;
        hx[idx] = tanhf(s + bh[n] + hx[idx]);   // hx holds xproj_t, overwritten with h_t
    }
}

// ============================================================================
// Launch: xproj -> step0 -> 511 step kernels (graph nodes = grid syncs)
// -> D2D copy of h_last.
// ============================================================================
extern "C" void kernel_launch(void* const* d_in, const int* in_sizes, int n_in,
                              void* d_out, int out_size)
{
    const float* x  = (const float*)d_in[0];
    const float* Wx = (const float*)d_in[1];
    const float* bx = (const float*)d_in[2];
    const float* Wh = (const float*)d_in[3];
    const float* bh = (const float*)d_in[4];
    float* out = (float*)d_out;

    xproj_kernel<<<dim3(HH / 64, (SS * BB) / 64), 256>>>(x, Wx, bx, out);
    step0_kernel<<<BH / 256, 256>>>(out, bh);
    for (int t = 1; t < SS; t++) {
        step_kernel<<<HH / 8, 256>>>(out + (size_t)(t - 1) * BH, Wh, bh,
                                     out + (size_t)t * BH);
    }
    cudaMemcpyAsync(out + (size_t)SS * BH, out + (size_t)(SS - 1) * BH,
                    (size_t)BH * sizeof(float), cudaMemcpyDeviceToDevice);
}

// round 6
// speedup vs baseline: 1.2042x; 1.2042x over previous
#include <cuda_runtime.h>
#include <math.h>

#define SS 512
#define BB 64
#define II 256
#define HH 1024
#define BH (BB*HH)
#define NB 128          // persistent CTAs (single wave, < 148 SMs)
#define NT 8            // output columns per CTA

// ============================================================================
// Grid-barrier counters: one slot per inter-step barrier (t = 0..510).
// Zeroed every launch via cudaMemsetAsync (a legal graph node).
// ============================================================================
__device__ unsigned g_bar[SS];

// ============================================================================
// Kernel 1: xproj[s*B+b, h] = dot(x[s,b,:], Wx[h,:]) + bx[h]
// GEMM M=32768, K=256, N=1024. Writes directly into d_out's h_seq region.
// ============================================================================
__global__ __launch_bounds__(256) void xproj_kernel(
    const float* __restrict__ x, const float* __restrict__ Wx,
    const float* __restrict__ bx, float* __restrict__ out)
{
    __shared__ __align__(16) float xs[16][68];
    __shared__ __align__(16) float ws[16][68];
    const int mBase = blockIdx.y * 64;
    const int nBase = blockIdx.x * 64;
    const int tid = threadIdx.x;
    const int tx = tid & 15;
    const int ty = tid >> 4;
    const int r = tid >> 2;
    const int c = tid & 3;

    float acc[4][4] = {};

    for (int k0 = 0; k0 < II; k0 += 16) {
        float4 xa = *(const float4*)&x [(size_t)(mBase + r) * II + k0 + c * 4];
        float4 wa = *(const float4*)&Wx[(size_t)(nBase + r) * II + k0 + c * 4];
        __syncthreads();
        xs[c*4+0][r] = xa.x; xs[c*4+1][r] = xa.y; xs[c*4+2][r] = xa.z; xs[c*4+3][r] = xa.w;
        ws[c*4+0][r] = wa.x; ws[c*4+1][r] = wa.y; ws[c*4+2][r] = wa.z; ws[c*4+3][r] = wa.w;
        __syncthreads();
        #pragma unroll
        for (int kk = 0; kk < 16; kk++) {
            float4 a = *(const float4*)&xs[kk][ty * 4];
            float4 b = *(const float4*)&ws[kk][tx * 4];
            acc[0][0] += a.x*b.x; acc[0][1] += a.x*b.y; acc[0][2] += a.x*b.z; acc[0][3] += a.x*b.w;
            acc[1][0] += a.y*b.x; acc[1][1] += a.y*b.y; acc[1][2] += a.y*b.z; acc[1][3] += a.y*b.w;
            acc[2][0] += a.z*b.x; acc[2][1] += a.z*b.y; acc[2][2] += a.z*b.z; acc[2][3] += a.z*b.w;
            acc[3][0] += a.w*b.x; acc[3][1] += a.w*b.y; acc[3][2] += a.w*b.z; acc[3][3] += a.w*b.w;
        }
    }

    #pragma unroll
    for (int i = 0; i < 4; i++) {
        #pragma unroll
        for (int j = 0; j < 4; j++) {
            int row = mBase + ty * 4 + i;
            int col = nBase + tx * 4 + j;
            out[(size_t)row * HH + col] = acc[i][j] + bx[col];
        }
    }
}

// ============================================================================
// Persistent RNN kernel: all 512 recurrence steps in one launch.
//
// Grid = 128 CTAs, each owns NT=8 columns of H for the whole sequence.
// SMEM: wsf[1024][8]  = this CTA's Wh slice, loaded ONCE (32 KB)
//       hs[64][68]    = h_prev K-chunk staging (17 KB), register-prefetched
//       red[8][512]   = split-K reduction scratch, ALIASES hs (disjoint in time)
// 256 threads = 8 k-split warps x (16 m_thr x 2 n_thr), 4x4 regs each.
// Between steps: software grid barrier (atomic arrive + volatile spin).
// Single wave guaranteed: 128 CTAs < 148 SMs, ~50KB smem < 228KB.
// ============================================================================
__global__ __launch_bounds__(256) void rnn_persistent(
    const float* __restrict__ Wh, const float* __restrict__ bh,
    float* __restrict__ out)
{
    extern __shared__ __align__(16) float sm[];
    float* wsf = sm;             // [1024][8]
    float* hs  = sm + 8192;      // [64][68]
    float* red = sm + 8192;      // [8][512], aliases hs

    const int tid   = threadIdx.x;
    const int nBase = blockIdx.x * NT;
    const int ks    = tid >> 5;
    const int lane  = tid & 31;
    const int n_thr = lane & 1;
    const int m_thr = lane >> 1;

    // ---- one-time Wh slice preload: 2048 float4 over 256 threads ----
    #pragma unroll
    for (int j = 0; j < 8; j++) {
        int lin = tid + j * 256;       // float4 index 0..2047
        int n  = lin >> 8;             // 0..7
        int k4 = lin & 255;            // 0..255
        float4 w = *(const float4*)&Wh[(size_t)(nBase + n) * HH + k4 * 4];
        wsf[(k4*4+0)*8 + n] = w.x;
        wsf[(k4*4+1)*8 + n] = w.y;
        wsf[(k4*4+2)*8 + n] = w.z;
        wsf[(k4*4+3)*8 + n] = w.w;
    }

    // bias for this thread's epilogue column ((tid+256)&7 == tid&7)
    const float bias = bh[nBase + (tid & 7)];

    // ---- step 0: h0 = 0  =>  h_seq[0] = tanh(xproj0 + bh), in place ----
    {
        float* h0 = out;
        #pragma unroll
        for (int r2 = 0; r2 < 2; r2++) {
            int o = tid + r2 * 256;            // m*8 + nl
            int m = o >> 3, nl = o & 7;
            size_t idx = (size_t)m * HH + nBase + nl;
            h0[idx] = tanhf(h0[idx] + bias);
        }
    }

    // grid barrier after step 0
    __threadfence();
    __syncthreads();
    if (tid == 0) {
        unsigned old = atomicAdd(&g_bar[0], 1u);
        if (old != NB - 1) {
            volatile unsigned* p = &g_bar[0];
            while (*p < NB) { }
        }
    }
    __syncthreads();

    // ---- steps 1..511 ----
    for (int t = 1; t < SS; t++) {
        const float* hp = out + (size_t)(t - 1) * BH;   // h_{t-1}
        float*       hx = out + (size_t)t * BH;         // xproj_t -> h_t

        float acc[4][4] = {};

        // prefetch chunk 0 of h_prev
        float4 ph[4];
        #pragma unroll
        for (int j = 0; j < 4; j++) {
            int lin = tid + j * 256;
            int m = lin >> 4, f = lin & 15;
            ph[j] = *(const float4*)&hp[(size_t)m * HH + f * 4];
        }

        for (int cblk = 0; cblk < HH / 64; cblk++) {
            __syncthreads();      // prev compute / red reads done with smem
            #pragma unroll
            for (int j = 0; j < 4; j++) {
                int lin = tid + j * 256;
                int m = lin >> 4, f = lin & 15;
                hs[(f*4+0)*68 + m] = ph[j].x;
                hs[(f*4+1)*68 + m] = ph[j].y;
                hs[(f*4+2)*68 + m] = ph[j].z;
                hs[(f*4+3)*68 + m] = ph[j].w;
            }
            __syncthreads();

            if (cblk + 1 < HH / 64) {
                int kNext = (cblk + 1) * 64;
                #pragma unroll
                for (int j = 0; j < 4; j++) {
                    int lin = tid + j * 256;
                    int m = lin >> 4, f = lin & 15;
                    ph[j] = *(const float4*)&hp[(size_t)m * HH + kNext + f * 4];
                }
            }

            const int kGlob = cblk * 64;
            #pragma unroll
            for (int kq = 0; kq < 8; kq++) {
                int k = ks * 8 + kq;
                float4 a = *(const float4*)&hs[k * 68 + m_thr * 4];
                float4 b = *(const float4*)&wsf[(kGlob + k) * 8 + n_thr * 4];
                acc[0][0] += a.x*b.x; acc[0][1] += a.x*b.y; acc[0][2] += a.x*b.z; acc[0][3] += a.x*b.w;
                acc[1][0] += a.y*b.x; acc[1][1] += a.y*b.y; acc[1][2] += a.y*b.z; acc[1][3] += a.y*b.w;
                acc[2][0] += a.z*b.x; acc[2][1] += a.z*b.y; acc[2][2] += a.z*b.z; acc[2][3] += a.z*b.w;
                acc[3][0] += a.w*b.x; acc[3][1] += a.w*b.y; acc[3][2] += a.w*b.z; acc[3][3] += a.w*b.w;
            }
        }

        // split-K reduction through red (aliases hs; guarded by syncthreads)
        __syncthreads();
        #pragma unroll
        for (int i = 0; i < 4; i++)
            #pragma unroll
            for (int j = 0; j < 4; j++)
                red[ks * 512 + (m_thr * 4 + i) * 8 + n_thr * 4 + j] = acc[i][j];
        __syncthreads();

        #pragma unroll
        for (int r2 = 0; r2 < 2; r2++) {
            int o = tid + r2 * 256;            // m*8 + nl
            float s = 0.f;
            #pragma unroll
            for (int p = 0; p < 8; p++) s += red[p * 512 + o];
            int m = o >> 3;
            int n = (o & 7) + nBase;
            size_t idx = (size_t)m * HH + n;
            hx[idx] = tanhf(s + bias + hx[idx]);
        }

        // grid barrier between steps (none after the last step)
        if (t < SS - 1) {
            __threadfence();
            __syncthreads();
            if (tid == 0) {
                unsigned old = atomicAdd(&g_bar[t], 1u);
                if (old != NB - 1) {
                    volatile unsigned* p = &g_bar[t];
                    while (*p < NB) { }
                }
            }
            __syncthreads();
        }
    }
}

// ============================================================================
// Launch: memset barriers -> xproj -> persistent RNN -> D2D h_last copy.
// ============================================================================
extern "C" void kernel_launch(void* const* d_in, const int* in_sizes, int n_in,
                              void* d_out, int out_size)
{
    const float* x  = (const float*)d_in[0];
    const float* Wx = (const float*)d_in[1];
    const float* bx = (const float*)d_in[2];
    const float* Wh = (const float*)d_in[3];
    const float* bh = (const float*)d_in[4];
    float* out = (float*)d_out;

    // zero the grid-barrier slots (graph-capturable memset node)
    void* bar_ptr = nullptr;
    cudaGetSymbolAddress(&bar_ptr, g_bar);
    cudaMemsetAsync(bar_ptr, 0, SS * sizeof(unsigned));

    const int smemBytes = (8192 + 64 * 68) * sizeof(float);   // 50176
    cudaFuncSetAttribute(rnn_persistent,
                         cudaFuncAttributeMaxDynamicSharedMemorySize, smemBytes);

    xproj_kernel<<<dim3(HH / 64, (SS * BB) / 64), 256>>>(x, Wx, bx, out);
    rnn_persistent<<<NB, 256, smemBytes>>>(Wh, bh, out);

    cudaMemcpyAsync(out + (size_t)SS * BH, out + (size_t)(SS - 1) * BH,
                    (size_t)BH * sizeof(float), cudaMemcpyDeviceToDevice);
}

// round 7
// speedup vs baseline: 2.3565x; 1.9569x over previous
#include <cuda_runtime.h>
#include <math.h>

#define SS 512
#define BB 64
#define II 256
#define HH 1024
#define BH (BB*HH)
#define NB 128          // persistent CTAs (single wave, < 148 SMs)
#define NT 8            // output columns per CTA
#define NTH 512         // threads per CTA (16 warps)

// ============================================================================
// Scratch: transposed h, double-buffered. hT[buf][k][m] (k-major).
// Grid-barrier counters, zeroed per launch via cudaMemsetAsync.
// ============================================================================
__device__ float g_hT[2][HH * BB];
__device__ unsigned g_bar[SS];

// ============================================================================
// Kernel 1: xproj[s*B+b, h] = dot(x[s,b,:], Wx[h,:]) + bx[h]
// GEMM M=32768, K=256, N=1024. Writes directly into d_out's h_seq region.
// ============================================================================
__global__ __launch_bounds__(256) void xproj_kernel(
    const float* __restrict__ x, const float* __restrict__ Wx,
    const float* __restrict__ bx, float* __restrict__ out)
{
    __shared__ __align__(16) float xs[16][68];
    __shared__ __align__(16) float ws[16][68];
    const int mBase = blockIdx.y * 64;
    const int nBase = blockIdx.x * 64;
    const int tid = threadIdx.x;
    const int tx = tid & 15;
    const int ty = tid >> 4;
    const int r = tid >> 2;
    const int c = tid & 3;

    float acc[4][4] = {};

    for (int k0 = 0; k0 < II; k0 += 16) {
        float4 xa = *(const float4*)&x [(size_t)(mBase + r) * II + k0 + c * 4];
        float4 wa = *(const float4*)&Wx[(size_t)(nBase + r) * II + k0 + c * 4];
        __syncthreads();
        xs[c*4+0][r] = xa.x; xs[c*4+1][r] = xa.y; xs[c*4+2][r] = xa.z; xs[c*4+3][r] = xa.w;
        ws[c*4+0][r] = wa.x; ws[c*4+1][r] = wa.y; ws[c*4+2][r] = wa.z; ws[c*4+3][r] = wa.w;
        __syncthreads();
        #pragma unroll
        for (int kk = 0; kk < 16; kk++) {
            float4 a = *(const float4*)&xs[kk][ty * 4];
            float4 b = *(const float4*)&ws[kk][tx * 4];
            acc[0][0] += a.x*b.x; acc[0][1] += a.x*b.y; acc[0][2] += a.x*b.z; acc[0][3] += a.x*b.w;
            acc[1][0] += a.y*b.x; acc[1][1] += a.y*b.y; acc[1][2] += a.y*b.z; acc[1][3] += a.y*b.w;
            acc[2][0] += a.z*b.x; acc[2][1] += a.z*b.y; acc[2][2] += a.z*b.z; acc[2][3] += a.z*b.w;
            acc[3][0] += a.w*b.x; acc[3][1] += a.w*b.y; acc[3][2] += a.w*b.z; acc[3][3] += a.w*b.w;
        }
    }

    #pragma unroll
    for (int i = 0; i < 4; i++) {
        #pragma unroll
        for (int j = 0; j < 4; j++) {
            int row = mBase + ty * 4 + i;
            int col = nBase + tx * 4 + j;
            out[(size_t)row * HH + col] = acc[i][j] + bx[col];
        }
    }
}

// ============================================================================
// Persistent RNN kernel: all 512 recurrence steps in one launch.
//
// Grid = 128 CTAs x 512 threads. Each CTA owns NT=8 columns of H.
// Threads: 16 k-split warps x (16 m_thr x 2 n_thr), 4x4 register tile.
// a-operand: float4 direct from transposed h (g_hT, L2 via __ldcg) — no
//            smem staging, no mainloop barriers.
// b-operand: Wh slice transposed in smem (loaded ONCE, reused 511 steps).
// Epilogue: 16-way split-K reduction in smem -> tanh -> write out + hT.
// Between steps: software grid barrier. Single wave: 128 CTAs < 148 SMs.
// ============================================================================
__global__ __launch_bounds__(NTH) void rnn_persistent(
    const float* __restrict__ Wh, const float* __restrict__ bh,
    float* __restrict__ out)
{
    extern __shared__ __align__(16) float sm[];
    float* wsf = sm;           // [1024][8]  Wh slice, [k][n]
    float* red = sm + 8192;    // [16][512]  split-K partials

    const int tid   = threadIdx.x;
    const int nBase = blockIdx.x * NT;
    const int ks    = tid >> 5;          // warp = k-split group 0..15
    const int lane  = tid & 31;
    const int n_thr = lane & 1;          // 0..1 (4 n each)
    const int m_thr = lane >> 1;         // 0..15 (4 m each)
    const int k0    = ks * 64;           // this warp's K range

    // ---- one-time Wh slice preload: 2048 float4 over 512 threads ----
    #pragma unroll
    for (int j = 0; j < 4; j++) {
        int lin = tid + j * NTH;        // float4 index 0..2047
        int n  = lin >> 8;              // 0..7
        int k4 = lin & 255;             // 0..255
        float4 w = *(const float4*)&Wh[(size_t)(nBase + n) * HH + k4 * 4];
        wsf[(k4*4+0)*8 + n] = w.x;
        wsf[(k4*4+1)*8 + n] = w.y;
        wsf[(k4*4+2)*8 + n] = w.z;
        wsf[(k4*4+3)*8 + n] = w.w;
    }

    // epilogue mapping: o = tid -> (m = o>>3, n_local = o&7)
    const int eo_m = tid >> 3;
    const int eo_n = tid & 7;
    const float bias = bh[nBase + eo_n];

    // ---- step 0: h0 = 0  =>  h_0 = tanh(xproj0 + bh); write out + hT[0] ----
    {
        size_t idx = (size_t)eo_m * HH + nBase + eo_n;
        float v = tanhf(out[idx] + bias);
        out[idx] = v;
        g_hT[0][(nBase + eo_n) * BB + eo_m] = v;
    }

    // grid barrier after step 0
    __threadfence();
    __syncthreads();
    if (tid == 0) {
        unsigned old = atomicAdd(&g_bar[0], 1u);
        if (old != NB - 1) {
            volatile unsigned* p = &g_bar[0];
            while (*p < NB) { }
        }
    }
    __syncthreads();

    // ---- steps 1..511 ----
    for (int t = 1; t < SS; t++) {
        const float* hT  = g_hT[(t - 1) & 1];        // [k][m], previous h
        float*       hTo = g_hT[t & 1];
        float*       hx  = out + (size_t)t * BH;     // xproj_t -> h_t

        float acc[4][4] = {};

        // register-pipelined a-loads (depth 4), b from smem
        const float* aBase = hT + (size_t)k0 * BB + m_thr * 4;
        float4 abuf[4];
        #pragma unroll
        for (int i = 0; i < 4; i++)
            abuf[i] = __ldcg((const float4*)(aBase + i * BB));

        #pragma unroll 4
        for (int kk = 0; kk < 64; kk++) {
            float4 a = abuf[kk & 3];
            if (kk + 4 < 64)
                abuf[kk & 3] = __ldcg((const float4*)(aBase + (kk + 4) * BB));
            float4 b = *(const float4*)&wsf[(k0 + kk) * 8 + n_thr * 4];
            acc[0][0] += a.x*b.x; acc[0][1] += a.x*b.y; acc[0][2] += a.x*b.z; acc[0][3] += a.x*b.w;
            acc[1][0] += a.y*b.x; acc[1][1] += a.y*b.y; acc[1][2] += a.y*b.z; acc[1][3] += a.y*b.w;
            acc[2][0] += a.z*b.x; acc[2][1] += a.z*b.y; acc[2][2] += a.z*b.z; acc[2][3] += a.z*b.w;
            acc[3][0] += a.w*b.x; acc[3][1] += a.w*b.y; acc[3][2] += a.w*b.z; acc[3][3] += a.w*b.w;
        }

        // split-K reduction through smem
        __syncthreads();
        #pragma unroll
        for (int i = 0; i < 4; i++)
            #pragma unroll
            for (int j = 0; j < 4; j++)
                red[ks * 512 + (m_thr * 4 + i) * 8 + n_thr * 4 + j] = acc[i][j];
        __syncthreads();

        {
            float s = 0.f;
            #pragma unroll
            for (int p = 0; p < 16; p++) s += red[p * 512 + tid];
            size_t idx = (size_t)eo_m * HH + nBase + eo_n;
            float v = tanhf(s + bias + hx[idx]);
            hx[idx] = v;
            hTo[(nBase + eo_n) * BB + eo_m] = v;
        }

        // grid barrier between steps (none after the last step)
        if (t < SS - 1) {
            __threadfence();
            __syncthreads();
            if (tid == 0) {
                unsigned old = atomicAdd(&g_bar[t], 1u);
                if (old != NB - 1) {
                    volatile unsigned* p = &g_bar[t];
                    while (*p < NB) { }
                }
            }
            __syncthreads();
        }
    }
}

// ============================================================================
// Launch: memset barriers -> xproj -> persistent RNN -> D2D h_last copy.
// ============================================================================
extern "C" void kernel_launch(void* const* d_in, const int* in_sizes, int n_in,
                              void* d_out, int out_size)
{
    const float* x  = (const float*)d_in[0];
    const float* Wx = (const float*)d_in[1];
    const float* bx = (const float*)d_in[2];
    const float* Wh = (const float*)d_in[3];
    const float* bh = (const float*)d_in[4];
    float* out = (float*)d_out;

    void* bar_ptr = nullptr;
    cudaGetSymbolAddress(&bar_ptr, g_bar);
    cudaMemsetAsync(bar_ptr, 0, SS * sizeof(unsigned));

    const int smemBytes = (8192 + 16 * 512) * sizeof(float);   // 64 KB
    cudaFuncSetAttribute(rnn_persistent,
                         cudaFuncAttributeMaxDynamicSharedMemorySize, smemBytes);

    xproj_kernel<<<dim3(HH / 64, (SS * BB) / 64), 256>>>(x, Wx, bx, out);
    rnn_persistent<<<NB, NTH, smemBytes>>>(Wh, bh, out);

    cudaMemcpyAsync(out + (size_t)SS * BH, out + (size_t)(SS - 1) * BH,
                    (size_t)BH * sizeof(float), cudaMemcpyDeviceToDevice);
}

// round 8
// speedup vs baseline: 2.4322x; 1.0321x over previous
#include <cuda_runtime.h>
#include <math.h>

#define SS 512
#define BB 64
#define II 256
#define HH 1024
#define BH (BB*HH)
#define NB 128          // persistent CTAs (single wave, < 148 SMs)
#define NT 8            // output columns per CTA
#define NTH 512         // threads per CTA (16 warps)

typedef unsigned long long u64;

// packed f32x2 FMA: d = a*b + d (full fp32 precision, 2 lanes per instr)
#define FMA2(d, a, b) \
    asm("fma.rn.f32x2 %0, %1, %2, %0;" : "+l"(d) : "l"(a), "l"(b))

// ============================================================================
// Scratch: transposed h, double-buffered. hT[buf][k][m] (k-major, m contig).
// Grid-barrier counters, zeroed per launch via cudaMemsetAsync.
// ============================================================================
__device__ __align__(16) float g_hT[2][HH * BB];
__device__ unsigned g_bar[SS];

// ============================================================================
// Kernel 1: xproj[s*B+b, h] = dot(x[s,b,:], Wx[h,:]) + bx[h]
// GEMM M=32768, K=256, N=1024. Writes directly into d_out's h_seq region.
// ============================================================================
__global__ __launch_bounds__(256) void xproj_kernel(
    const float* __restrict__ x, const float* __restrict__ Wx,
    const float* __restrict__ bx, float* __restrict__ out)
{
    __shared__ __align__(16) float xs[16][68];
    __shared__ __align__(16) float ws[16][68];
    const int mBase = blockIdx.y * 64;
    const int nBase = blockIdx.x * 64;
    const int tid = threadIdx.x;
    const int tx = tid & 15;
    const int ty = tid >> 4;
    const int r = tid >> 2;
    const int c = tid & 3;

    float acc[4][4] = {};

    for (int k0 = 0; k0 < II; k0 += 16) {
        float4 xa = *(const float4*)&x [(size_t)(mBase + r) * II + k0 + c * 4];
        float4 wa = *(const float4*)&Wx[(size_t)(nBase + r) * II + k0 + c * 4];
        __syncthreads();
        xs[c*4+0][r] = xa.x; xs[c*4+1][r] = xa.y; xs[c*4+2][r] = xa.z; xs[c*4+3][r] = xa.w;
        ws[c*4+0][r] = wa.x; ws[c*4+1][r] = wa.y; ws[c*4+2][r] = wa.z; ws[c*4+3][r] = wa.w;
        __syncthreads();
        #pragma unroll
        for (int kk = 0; kk < 16; kk++) {
            float4 a = *(const float4*)&xs[kk][ty * 4];
            float4 b = *(const float4*)&ws[kk][tx * 4];
            acc[0][0] += a.x*b.x; acc[0][1] += a.x*b.y; acc[0][2] += a.x*b.z; acc[0][3] += a.x*b.w;
            acc[1][0] += a.y*b.x; acc[1][1] += a.y*b.y; acc[1][2] += a.y*b.z; acc[1][3] += a.y*b.w;
            acc[2][0] += a.z*b.x; acc[2][1] += a.z*b.y; acc[2][2] += a.z*b.z; acc[2][3] += a.z*b.w;
            acc[3][0] += a.w*b.x; acc[3][1] += a.w*b.y; acc[3][2] += a.w*b.z; acc[3][3] += a.w*b.w;
        }
    }

    #pragma unroll
    for (int i = 0; i < 4; i++) {
        #pragma unroll
        for (int j = 0; j < 4; j++) {
            int row = mBase + ty * 4 + i;
            int col = nBase + tx * 4 + j;
            out[(size_t)row * HH + col] = acc[i][j] + bx[col];
        }
    }
}

// ============================================================================
// Persistent RNN kernel: all 512 recurrence steps, FFMA2 (f32x2) mainloop.
//
// 128 CTAs x 512 threads (16 k-split warps x 16 m_thr x 2 n_thr).
// Per thread: 4 m x 4 n tile, accumulators packed over m (2 m-pairs x 4 n).
//   a: ulonglong2 LDG from hT (k-major) = two natural {h[m],h[m+1]} pairs.
//   b: Wh pre-DUPLICATED in smem as {w,w} pairs (64 KB, loaded once);
//      one LDS.128 yields dup-pairs for two n.
// Inner iter: 8 FFMA2 + 2 LDS.128 + 1 LDG.128.
// Epilogue: 16-way split-K reduction in smem -> tanh -> write out + hT.
// ============================================================================
__global__ __launch_bounds__(NTH) void rnn_persistent(
    const float* __restrict__ Wh, const float* __restrict__ bh,
    float* __restrict__ out)
{
    extern __shared__ __align__(16) float sm[];
    float* wsf2 = sm;             // [1024][8][2]  Wh dup-pairs: 16384 floats
    float* red  = sm + 16384;     // [16][512]     split-K partials

    const int tid   = threadIdx.x;
    const int nBase = blockIdx.x * NT;
    const int ks    = tid >> 5;          // warp = k-split group 0..15
    const int lane  = tid & 31;
    const int n_thr = lane & 1;          // 0..1 (4 n each)
    const int m_thr = lane >> 1;         // 0..15 (4 m each)
    const int k0    = ks * 64;           // this warp's K range

    // ---- one-time Wh slice preload, duplicated: wsf2[(k*8+n)*2 + {0,1}] ----
    #pragma unroll
    for (int j = 0; j < 4; j++) {
        int lin = tid + j * NTH;        // float4 index 0..2047
        int n  = lin >> 8;              // 0..7
        int k4 = lin & 255;             // 0..255
        float4 w = *(const float4*)&Wh[(size_t)(nBase + n) * HH + k4 * 4];
        int b0 = ((k4*4+0)*8 + n)*2;  wsf2[b0]   = w.x; wsf2[b0+1] = w.x;
        int b1 = ((k4*4+1)*8 + n)*2;  wsf2[b1]   = w.y; wsf2[b1+1] = w.y;
        int b2 = ((k4*4+2)*8 + n)*2;  wsf2[b2]   = w.z; wsf2[b2+1] = w.z;
        int b3 = ((k4*4+3)*8 + n)*2;  wsf2[b3]   = w.w; wsf2[b3+1] = w.w;
    }

    // epilogue mapping: o = tid -> (m = o>>3, n_local = o&7)
    const int eo_m = tid >> 3;
    const int eo_n = tid & 7;
    const float bias = bh[nBase + eo_n];

    // ---- step 0: h0 = 0  =>  h_0 = tanh(xproj0 + bh); write out + hT[0] ----
    {
        size_t idx = (size_t)eo_m * HH + nBase + eo_n;
        float v = tanhf(out[idx] + bias);
        out[idx] = v;
        g_hT[0][(nBase + eo_n) * BB + eo_m] = v;
    }

    // grid barrier after step 0
    __threadfence();
    __syncthreads();
    if (tid == 0) {
        unsigned old = atomicAdd(&g_bar[0], 1u);
        if (old != NB - 1) {
            volatile unsigned* p = &g_bar[0];
            while (*p < NB) { }
        }
    }
    __syncthreads();

    // ---- steps 1..511 ----
    for (int t = 1; t < SS; t++) {
        const float* hT  = g_hT[(t - 1) & 1];        // [k][m], previous h
        float*       hTo = g_hT[t & 1];
        float*       hx  = out + (size_t)t * BH;     // xproj_t -> h_t

        // acc2[n][p]: n = 0..3 (col n_thr*4+n), p = m-pair (m = m_thr*4+2p)
        u64 acc2[4][2] = {};

        const float* aBase = hT + (size_t)k0 * BB + m_thr * 4;
        const float* bBase = wsf2 + (k0 * 8 + n_thr * 4) * 2;

        // register pipeline depth 4
        ulonglong2 abuf[4];
        #pragma unroll
        for (int i = 0; i < 4; i++)
            abuf[i] = __ldcg((const ulonglong2*)(aBase + i * BB));

        #pragma unroll 4
        for (int kk = 0; kk < 60; kk++) {
            ulonglong2 av = abuf[kk & 3];
            abuf[kk & 3] = __ldcg((const ulonglong2*)(aBase + (kk + 4) * BB));
            ulonglong2 b01 = *(const ulonglong2*)(bBase + kk * 16);
            ulonglong2 b23 = *(const ulonglong2*)(bBase + kk * 16 + 4);
            FMA2(acc2[0][0], av.x, b01.x); FMA2(acc2[0][1], av.y, b01.x);
            FMA2(acc2[1][0], av.x, b01.y); FMA2(acc2[1][1], av.y, b01.y);
            FMA2(acc2[2][0], av.x, b23.x); FMA2(acc2[2][1], av.y, b23.x);
            FMA2(acc2[3][0], av.x, b23.y); FMA2(acc2[3][1], av.y, b23.y);
        }
        #pragma unroll
        for (int kk = 60; kk < 64; kk++) {
            ulonglong2 av = abuf[kk & 3];
            ulonglong2 b01 = *(const ulonglong2*)(bBase + kk * 16);
            ulonglong2 b23 = *(const ulonglong2*)(bBase + kk * 16 + 4);
            FMA2(acc2[0][0], av.x, b01.x); FMA2(acc2[0][1], av.y, b01.x);
            FMA2(acc2[1][0], av.x, b01.y); FMA2(acc2[1][1], av.y, b01.y);
            FMA2(acc2[2][0], av.x, b23.x); FMA2(acc2[2][1], av.y, b23.x);
            FMA2(acc2[3][0], av.x, b23.y); FMA2(acc2[3][1], av.y, b23.y);
        }

        // split-K reduction through smem
        __syncthreads();
        #pragma unroll
        for (int j = 0; j < 4; j++) {
            #pragma unroll
            for (int p = 0; p < 2; p++) {
                u64 v = acc2[j][p];
                float lo = __uint_as_float((unsigned)(v & 0xFFFFFFFFu));
                float hi = __uint_as_float((unsigned)(v >> 32));
                int m = m_thr * 4 + 2 * p;
                red[ks * 512 + (m    ) * 8 + n_thr * 4 + j] = lo;
                red[ks * 512 + (m + 1) * 8 + n_thr * 4 + j] = hi;
            }
        }
        __syncthreads();

        {
            float s = 0.f;
            #pragma unroll
            for (int p = 0; p < 16; p++) s += red[p * 512 + tid];
            size_t idx = (size_t)eo_m * HH + nBase + eo_n;
            float v = tanhf(s + bias + hx[idx]);
            hx[idx] = v;
            hTo[(nBase + eo_n) * BB + eo_m] = v;
        }

        // grid barrier between steps (none after the last step)
        if (t < SS - 1) {
            __threadfence();
            __syncthreads();
            if (tid == 0) {
                unsigned old = atomicAdd(&g_bar[t], 1u);
                if (old != NB - 1) {
                    volatile unsigned* p = &g_bar[t];
                    while (*p < NB) { }
                }
            }
            __syncthreads();
        }
    }
}

// ============================================================================
// Launch: memset barriers -> xproj -> persistent RNN -> D2D h_last copy.
// ============================================================================
extern "C" void kernel_launch(void* const* d_in, const int* in_sizes, int n_in,
                              void* d_out, int out_size)
{
    const float* x  = (const float*)d_in[0];
    const float* Wx = (const float*)d_in[1];
    const float* bx = (const float*)d_in[2];
    const float* Wh = (const float*)d_in[3];
    const float* bh = (const float*)d_in[4];
    float* out = (float*)d_out;

    void* bar_ptr = nullptr;
    cudaGetSymbolAddress(&bar_ptr, g_bar);
    cudaMemsetAsync(bar_ptr, 0, SS * sizeof(unsigned));

    const int smemBytes = (16384 + 16 * 512) * sizeof(float);   // 96 KB
    cudaFuncSetAttribute(rnn_persistent,
                         cudaFuncAttributeMaxDynamicSharedMemorySize, smemBytes);

    xproj_kernel<<<dim3(HH / 64, (SS * BB) / 64), 256>>>(x, Wx, bx, out);
    rnn_persistent<<<NB, NTH, smemBytes>>>(Wh, bh, out);

    cudaMemcpyAsync(out + (size_t)SS * BH, out + (size_t)(SS - 1) * BH,
                    (size_t)BH * sizeof(float), cudaMemcpyDeviceToDevice);
}

// round 9
// speedup vs baseline: 2.4470x; 1.0061x over previous
#include <cuda_runtime.h>
#include <math.h>

#define SS 512
#define BB 64
#define II 256
#define HH 1024
#define BH (BB*HH)
#define NB 128          // persistent CTAs (single wave, < 148 SMs)
#define NT 8            // output columns per CTA
#define NTH 1024        // threads per CTA (32 warps, occ 50%)

typedef unsigned long long u64;

// packed f32x2 FMA: d = a*b + d (full fp32 precision, 2 lanes per instr)
#define FMA2(d, a, b) \
    asm("fma.rn.f32x2 %0, %1, %2, %0;" : "+l"(d) : "l"(a), "l"(b))

// ============================================================================
// Scratch: transposed h, double-buffered. hT[buf][k][m] (k-major, m contig).
// Grid-barrier counters, zeroed per launch via cudaMemsetAsync.
// ============================================================================
__device__ __align__(16) float g_hT[2][HH * BB];
__device__ unsigned g_bar[SS];

// ============================================================================
// Kernel 1: xproj[s*B+b, h] = dot(x[s,b,:], Wx[h,:]) + bx[h]
// ============================================================================
__global__ __launch_bounds__(256) void xproj_kernel(
    const float* __restrict__ x, const float* __restrict__ Wx,
    const float* __restrict__ bx, float* __restrict__ out)
{
    __shared__ __align__(16) float xs[16][68];
    __shared__ __align__(16) float ws[16][68];
    const int mBase = blockIdx.y * 64;
    const int nBase = blockIdx.x * 64;
    const int tid = threadIdx.x;
    const int tx = tid & 15;
    const int ty = tid >> 4;
    const int r = tid >> 2;
    const int c = tid & 3;

    float acc[4][4] = {};

    for (int k0 = 0; k0 < II; k0 += 16) {
        float4 xa = *(const float4*)&x [(size_t)(mBase + r) * II + k0 + c * 4];
        float4 wa = *(const float4*)&Wx[(size_t)(nBase + r) * II + k0 + c * 4];
        __syncthreads();
        xs[c*4+0][r] = xa.x; xs[c*4+1][r] = xa.y; xs[c*4+2][r] = xa.z; xs[c*4+3][r] = xa.w;
        ws[c*4+0][r] = wa.x; ws[c*4+1][r] = wa.y; ws[c*4+2][r] = wa.z; ws[c*4+3][r] = wa.w;
        __syncthreads();
        #pragma unroll
        for (int kk = 0; kk < 16; kk++) {
            float4 a = *(const float4*)&xs[kk][ty * 4];
            float4 b = *(const float4*)&ws[kk][tx * 4];
            acc[0][0] += a.x*b.x; acc[0][1] += a.x*b.y; acc[0][2] += a.x*b.z; acc[0][3] += a.x*b.w;
            acc[1][0] += a.y*b.x; acc[1][1] += a.y*b.y; acc[1][2] += a.y*b.z; acc[1][3] += a.y*b.w;
            acc[2][0] += a.z*b.x; acc[2][1] += a.z*b.y; acc[2][2] += a.z*b.z; acc[2][3] += a.z*b.w;
            acc[3][0] += a.w*b.x; acc[3][1] += a.w*b.y; acc[3][2] += a.w*b.z; acc[3][3] += a.w*b.w;
        }
    }

    #pragma unroll
    for (int i = 0; i < 4; i++) {
        #pragma unroll
        for (int j = 0; j < 4; j++) {
            int row = mBase + ty * 4 + i;
            int col = nBase + tx * 4 + j;
            out[(size_t)row * HH + col] = acc[i][j] + bx[col];
        }
    }
}

// ============================================================================
// Persistent RNN kernel: all 512 steps, FFMA2 mainloop, 32 warps/CTA.
// ============================================================================
__global__ __launch_bounds__(NTH) void rnn_persistent(
    const float* __restrict__ Wh, const float* __restrict__ bh,
    float* __restrict__ out)
{
    extern __shared__ __align__(16) float sm[];
    float* wsf2 = sm;             // [1024][8][2]  Wh dup-pairs: 16384 floats
    float* red  = sm + 16384;     // [32][512]     split-K partials

    const int tid   = threadIdx.x;
    const int nBase = blockIdx.x * NT;
    const int ks    = tid >> 5;          // warp = k-split group 0..31
    const int lane  = tid & 31;
    const int n_thr = lane & 1;          // 0..1 (4 n each)
    const int m_thr = lane >> 1;         // 0..15 (4 m each)
    const int k0    = ks * 32;           // this warp's K range (32 wide)

    // ---- one-time Wh slice preload, duplicated: wsf2[(k*8+n)*2 + {0,1}] ----
    #pragma unroll
    for (int j = 0; j < 2; j++) {
        int lin = tid + j * NTH;        // float4 index 0..2047
        int n  = lin >> 8;              // 0..7
        int k4 = lin & 255;             // 0..255
        float4 w = *(const float4*)&Wh[(size_t)(nBase + n) * HH + k4 * 4];
        int b0 = ((k4*4+0)*8 + n)*2;  wsf2[b0]   = w.x; wsf2[b0+1] = w.x;
        int b1 = ((k4*4+1)*8 + n)*2;  wsf2[b1]   = w.y; wsf2[b1+1] = w.y;
        int b2 = ((k4*4+2)*8 + n)*2;  wsf2[b2]   = w.z; wsf2[b2+1] = w.z;
        int b3 = ((k4*4+3)*8 + n)*2;  wsf2[b3]   = w.w; wsf2[b3+1] = w.w;
    }

    // epilogue mapping (tid < 512): o = tid -> (m = o>>3, n_local = o&7)
    const int eo_m = (tid & 511) >> 3;
    const int eo_n = tid & 7;
    const float bias = bh[nBase + eo_n];
    const size_t eo_idx = (size_t)eo_m * HH + nBase + eo_n;
    const int hT_idx = (nBase + eo_n) * BB + eo_m;

    // ---- step 0: h0 = 0  =>  h_0 = tanh(xproj0 + bh); write out + hT[0] ----
    if (tid < 512) {
        float v = tanhf(out[eo_idx] + bias);
        out[eo_idx] = v;
        g_hT[0][hT_idx] = v;
    }

    __threadfence();
    __syncthreads();
    if (tid == 0) {
        unsigned old = atomicAdd(&g_bar[0], 1u);
        if (old != NB - 1) {
            volatile unsigned* p = &g_bar[0];
            while (*p < NB) { }
        }
    }
    __syncthreads();

    // ---- steps 1..511 ----
    for (int t = 1; t < SS; t++) {
        const float* hT  = g_hT[(t - 1) & 1];
        float*       hTo = g_hT[t & 1];
        float*       hx  = out + (size_t)t * BH;

        // prefetch this thread's xproj term early (hides DRAM/L2 latency)
        float xp = 0.f;
        if (tid < 512) xp = __ldcg(&hx[eo_idx]);

        u64 acc2[4][2] = {};

        const float* aBase = hT + (size_t)k0 * BB + m_thr * 4;
        const float* bBase = wsf2 + (k0 * 8 + n_thr * 4) * 2;

        ulonglong2 abuf[4];
        #pragma unroll
        for (int i = 0; i < 4; i++)
            abuf[i] = __ldcg((const ulonglong2*)(aBase + i * BB));

        #pragma unroll 4
        for (int kk = 0; kk < 28; kk++) {
            ulonglong2 av = abuf[kk & 3];
            abuf[kk & 3] = __ldcg((const ulonglong2*)(aBase + (kk + 4) * BB));
            ulonglong2 b01 = *(const ulonglong2*)(bBase + kk * 16);
            ulonglong2 b23 = *(const ulonglong2*)(bBase + kk * 16 + 4);
            FMA2(acc2[0][0], av.x, b01.x); FMA2(acc2[0][1], av.y, b01.x);
            FMA2(acc2[1][0], av.x, b01.y); FMA2(acc2[1][1], av.y, b01.y);
            FMA2(acc2[2][0], av.x, b23.x); FMA2(acc2[2][1], av.y, b23.x);
            FMA2(acc2[3][0], av.x, b23.y); FMA2(acc2[3][1], av.y, b23.y);
        }
        #pragma unroll
        for (int kk = 28; kk < 32; kk++) {
            ulonglong2 av = abuf[kk & 3];
            ulonglong2 b01 = *(const ulonglong2*)(bBase + kk * 16);
            ulonglong2 b23 = *(const ulonglong2*)(bBase + kk * 16 + 4);
            FMA2(acc2[0][0], av.x, b01.x); FMA2(acc2[0][1], av.y, b01.x);
            FMA2(acc2[1][0], av.x, b01.y); FMA2(acc2[1][1], av.y, b01.y);
            FMA2(acc2[2][0], av.x, b23.x); FMA2(acc2[2][1], av.y, b23.x);
            FMA2(acc2[3][0], av.x, b23.y); FMA2(acc2[3][1], av.y, b23.y);
        }

        // split-K reduction through smem
        __syncthreads();
        #pragma unroll
        for (int j = 0; j < 4; j++) {
            #pragma unroll
            for (int p = 0; p < 2; p++) {
                u64 v = acc2[j][p];
                float lo = __uint_as_float((unsigned)(v & 0xFFFFFFFFu));
                float hi = __uint_as_float((unsigned)(v >> 32));
                int m = m_thr * 4 + 2 * p;
                red[ks * 512 + (m    ) * 8 + n_thr * 4 + j] = lo;
                red[ks * 512 + (m + 1) * 8 + n_thr * 4 + j] = hi;
            }
        }
        __syncthreads();

        if (tid < 512) {
            float s = 0.f;
            #pragma unroll
            for (int p = 0; p < 32; p++) s += red[p * 512 + tid];
            float v = tanhf(s + bias + xp);
            hx[eo_idx] = v;
            hTo[hT_idx] = v;
        }

        if (t < SS - 1) {
            __threadfence();
            __syncthreads();
            if (tid == 0) {
                unsigned old = atomicAdd(&g_bar[t], 1u);
                if (old != NB - 1) {
                    volatile unsigned* p = &g_bar[t];
                    while (*p < NB) { }
                }
            }
            __syncthreads();
        }
    }
}

// ============================================================================
// Launch: memset barriers -> xproj -> persistent RNN -> D2D h_last copy.
// ============================================================================
extern "C" void kernel_launch(void* const* d_in, const int* in_sizes, int n_in,
                              void* d_out, int out_size)
{
    const float* x  = (const float*)d_in[0];
    const float* Wx = (const float*)d_in[1];
    const float* bx = (const float*)d_in[2];
    const float* Wh = (const float*)d_in[3];
    const float* bh = (const float*)d_in[4];
    float* out = (float*)d_out;

    void* bar_ptr = nullptr;
    cudaGetSymbolAddress(&bar_ptr, g_bar);
    cudaMemsetAsync(bar_ptr, 0, SS * sizeof(unsigned));

    const int smemBytes = (16384 + 32 * 512) * sizeof(float);   // 128 KB
    cudaFuncSetAttribute(rnn_persistent,
                         cudaFuncAttributeMaxDynamicSharedMemorySize, smemBytes);

    xproj_kernel<<<dim3(HH / 64, (SS * BB) / 64), 256>>>(x, Wx, bx, out);
    rnn_persistent<<<NB, NTH, smemBytes>>>(Wh, bh, out);

    cudaMemcpyAsync(out + (size_t)SS * BH, out + (size_t)(SS - 1) * BH,
                    (size_t)BH * sizeof(float), cudaMemcpyDeviceToDevice);
}

// round 11
// speedup vs baseline: 2.5906x; 1.0587x over previous
#include <cuda_runtime.h>
#include <math.h>

#define SS 512
#define BB 64
#define II 256
#define HH 1024
#define BH (BB*HH)
#define NB 128          // persistent CTAs (single wave, < 148 SMs)
#define NT 8            // output columns per CTA
#define NTH 512         // threads per CTA (16 warps)
#define KW  64          // K-slice per warp
#define NWARP 16

typedef unsigned long long u64;

// packed f32x2 FMA: d = a*b + d (full fp32 precision, 2 lanes per instr)
#define FMA2(d, a, b) \
    asm("fma.rn.f32x2 %0, %1, %2, %0;" : "+l"(d) : "l"(a), "l"(b))

// ============================================================================
// Scratch: transposed h, double-buffered. hT[buf][k][m] (k-major, m contig).
// Grid-barrier counters, zeroed per launch via cudaMemsetAsync.
// ============================================================================
__device__ __align__(16) float g_hT[2][HH * BB];
__device__ unsigned g_bar[SS];

// ============================================================================
// Kernel 1: xproj[s*B+b, h] = dot(x[s,b,:], Wx[h,:]) + bx[h]
// ============================================================================
__global__ __launch_bounds__(256) void xproj_kernel(
    const float* __restrict__ x, const float* __restrict__ Wx,
    const float* __restrict__ bx, float* __restrict__ out)
{
    __shared__ __align__(16) float xs[16][68];
    __shared__ __align__(16) float ws[16][68];
    const int mBase = blockIdx.y * 64;
    const int nBase = blockIdx.x * 64;
    const int tid = threadIdx.x;
    const int tx = tid & 15;
    const int ty = tid >> 4;
    const int r = tid >> 2;
    const int c = tid & 3;

    float acc[4][4] = {};

    for (int k0 = 0; k0 < II; k0 += 16) {
        float4 xa = *(const float4*)&x [(size_t)(mBase + r) * II + k0 + c * 4];
        float4 wa = *(const float4*)&Wx[(size_t)(nBase + r) * II + k0 + c * 4];
        __syncthreads();
        xs[c*4+0][r] = xa.x; xs[c*4+1][r] = xa.y; xs[c*4+2][r] = xa.z; xs[c*4+3][r] = xa.w;
        ws[c*4+0][r] = wa.x; ws[c*4+1][r] = wa.y; ws[c*4+2][r] = wa.z; ws[c*4+3][r] = wa.w;
        __syncthreads();
        #pragma unroll
        for (int kk = 0; kk < 16; kk++) {
            float4 a = *(const float4*)&xs[kk][ty * 4];
            float4 b = *(const float4*)&ws[kk][tx * 4];
            acc[0][0] += a.x*b.x; acc[0][1] += a.x*b.y; acc[0][2] += a.x*b.z; acc[0][3] += a.x*b.w;
            acc[1][0] += a.y*b.x; acc[1][1] += a.y*b.y; acc[1][2] += a.y*b.z; acc[1][3] += a.y*b.w;
            acc[2][0] += a.z*b.x; acc[2][1] += a.z*b.y; acc[2][2] += a.z*b.z; acc[2][3] += a.z*b.w;
            acc[3][0] += a.w*b.x; acc[3][1] += a.w*b.y; acc[3][2] += a.w*b.z; acc[3][3] += a.w*b.w;
        }
    }

    #pragma unroll
    for (int i = 0; i < 4; i++) {
        #pragma unroll
        for (int j = 0; j < 4; j++) {
            int row = mBase + ty * 4 + i;
            int col = nBase + tx * 4 + j;
            out[(size_t)row * HH + col] = acc[i][j] + bx[col];
        }
    }
}

// ============================================================================
// Persistent RNN kernel: all 512 steps. 16 warps x (16 m_thr x 2 n_thr),
// 4m x 4n per thread (m-packed FFMA2), K=64 per warp, LDG depth-8 pipeline.
// Reduction carried as packed f32x2 (u64): STS.128 stores, scalar-float sum.
// Exact tanhf, proven atomicAdd grid barrier.
// ============================================================================
__global__ __launch_bounds__(NTH) void rnn_persistent(
    const float* __restrict__ Wh, const float* __restrict__ bh,
    float* __restrict__ out)
{
    extern __shared__ __align__(16) float sm[];
    float* wsf2 = sm;                       // [1024][8][2] Wh dup-pairs (64 KB)
    u64*   red2 = (u64*)(sm + 16384);       // [16][256]    packed partials (32 KB)

    const int tid   = threadIdx.x;
    const int nBase = blockIdx.x * NT;
    const int ks    = tid >> 5;             // warp = k-split group 0..15
    const int lane  = tid & 31;
    const int n_thr = lane & 1;             // 0..1 (4 n each)
    const int m_thr = lane >> 1;            // 0..15 (4 m each = 2 m-pairs)
    const int k0    = ks * KW;              // this warp's K range (64 wide)

    // ---- one-time Wh slice preload, duplicated: wsf2[(k*8+n)*2 + {0,1}] ----
    #pragma unroll
    for (int j = 0; j < 4; j++) {
        int lin = tid + j * NTH;            // float4 index 0..2047
        int n  = lin >> 8;                  // 0..7
        int k4 = lin & 255;                 // 0..255
        float4 w = *(const float4*)&Wh[(size_t)(nBase + n) * HH + k4 * 4];
        int b0 = ((k4*4+0)*8 + n)*2;  wsf2[b0]   = w.x; wsf2[b0+1] = w.x;
        int b1 = ((k4*4+1)*8 + n)*2;  wsf2[b1]   = w.y; wsf2[b1+1] = w.y;
        int b2 = ((k4*4+2)*8 + n)*2;  wsf2[b2]   = w.z; wsf2[b2+1] = w.z;
        int b3 = ((k4*4+3)*8 + n)*2;  wsf2[b3]   = w.w; wsf2[b3+1] = w.w;
    }

    // epilogue mapping: o = tid -> (m = o>>3, n_local = o&7)
    const int eo_m  = tid >> 3;
    const int eo_n  = tid & 7;
    const int eo_mp = eo_m >> 1;            // m-pair index
    const int eo_hf = eo_m & 1;             // which half of the pair
    const float bias = bh[nBase + eo_n];
    const size_t eo_idx = (size_t)eo_m * HH + nBase + eo_n;
    const int hT_idx = (nBase + eo_n) * BB + eo_m;
    // scalar view of packed partials for the final sum
    const float* redf = (const float*)red2;
    const int red_off = (eo_mp * 8 + eo_n) * 2 + eo_hf;

    // ---- step 0: h0 = 0  =>  h_0 = tanh(xproj0 + bh); write out + hT[0] ----
    {
        float v = tanhf(out[eo_idx] + bias);
        out[eo_idx] = v;
        g_hT[0][hT_idx] = v;
    }

    __threadfence();
    __syncthreads();
    if (tid == 0) {
        unsigned old = atomicAdd(&g_bar[0], 1u);
        if (old != NB - 1) {
            volatile unsigned* p = &g_bar[0];
            while (*p < NB) { }
        }
    }
    __syncthreads();

    // ---- steps 1..511 ----
    for (int t = 1; t < SS; t++) {
        const float* hT  = g_hT[(t - 1) & 1];
        float*       hTo = g_hT[t & 1];
        float*       hx  = out + (size_t)t * BH;

        // prefetch this thread's xproj term early (hides DRAM/L2 latency)
        float xp = __ldcg(&hx[eo_idx]);

        // acc2[n][p]: n = 0..3 (col n_thr*4+n), p = m-pair (m = m_thr*4+2p)
        u64 acc2[4][2] = {};

        const float* aBase = hT + (size_t)k0 * BB + m_thr * 4;
        const float* bBase = wsf2 + (k0 * 8 + n_thr * 4) * 2;

        // register pipeline depth 8 (covers L2 latency even at ramp)
        ulonglong2 abuf[8];
        #pragma unroll
        for (int i = 0; i < 8; i++)
            abuf[i] = __ldcg((const ulonglong2*)(aBase + i * BB));

        #pragma unroll 8
        for (int kk = 0; kk < KW - 8; kk++) {
            ulonglong2 av = abuf[kk & 7];
            abuf[kk & 7] = __ldcg((const ulonglong2*)(aBase + (kk + 8) * BB));
            ulonglong2 b01 = *(const ulonglong2*)(bBase + kk * 16);
            ulonglong2 b23 = *(const ulonglong2*)(bBase + kk * 16 + 4);
            FMA2(acc2[0][0], av.x, b01.x); FMA2(acc2[0][1], av.y, b01.x);
            FMA2(acc2[1][0], av.x, b01.y); FMA2(acc2[1][1], av.y, b01.y);
            FMA2(acc2[2][0], av.x, b23.x); FMA2(acc2[2][1], av.y, b23.x);
            FMA2(acc2[3][0], av.x, b23.y); FMA2(acc2[3][1], av.y, b23.y);
        }
        #pragma unroll
        for (int kk = KW - 8; kk < KW; kk++) {
            ulonglong2 av = abuf[kk & 7];
            ulonglong2 b01 = *(const ulonglong2*)(bBase + kk * 16);
            ulonglong2 b23 = *(const ulonglong2*)(bBase + kk * 16 + 4);
            FMA2(acc2[0][0], av.x, b01.x); FMA2(acc2[0][1], av.y, b01.x);
            FMA2(acc2[1][0], av.x, b01.y); FMA2(acc2[1][1], av.y, b01.y);
            FMA2(acc2[2][0], av.x, b23.x); FMA2(acc2[2][1], av.y, b23.x);
            FMA2(acc2[3][0], av.x, b23.y); FMA2(acc2[3][1], av.y, b23.y);
        }

        // split-K reduction: store packed pairs (2x STS.128 per thread)
        // layout: red2[ks*256 + m_pair*8 + n]  where m_pair = m_thr*2+p
        __syncthreads();
        #pragma unroll
        for (int p = 0; p < 2; p++) {
            int base = ks * 256 + (m_thr * 2 + p) * 8 + n_thr * 4;
            ulonglong2 v01; v01.x = acc2[0][p]; v01.y = acc2[1][p];
            ulonglong2 v23; v23.x = acc2[2][p]; v23.y = acc2[3][p];
            *(ulonglong2*)&red2[base]     = v01;
            *(ulonglong2*)&red2[base + 2] = v23;
        }
        __syncthreads();

        // final sum: 512 threads, one output each, scalar reads of packed red
        {
            float s = 0.f;
            #pragma unroll
            for (int p = 0; p < NWARP; p++) s += redf[p * 512 + red_off];
            float v = tanhf(s + bias + xp);
            hx[eo_idx] = v;
            hTo[hT_idx] = v;
        }

        // grid barrier between steps (none after the last step)
        if (t < SS - 1) {
            __threadfence();
            __syncthreads();
            if (tid == 0) {
                unsigned old = atomicAdd(&g_bar[t], 1u);
                if (old != NB - 1) {
                    volatile unsigned* p = &g_bar[t];
                    while (*p < NB) { }
                }
            }
            __syncthreads();
        }
    }
}

// ============================================================================
// Launch: memset barriers -> xproj -> persistent RNN -> D2D h_last copy.
// ============================================================================
extern "C" void kernel_launch(void* const* d_in, const int* in_sizes, int n_in,
                              void* d_out, int out_size)
{
    const float* x  = (const float*)d_in[0];
    const float* Wx = (const float*)d_in[1];
    const float* bx = (const float*)d_in[2];
    const float* Wh = (const float*)d_in[3];
    const float* bh = (const float*)d_in[4];
    float* out = (float*)d_out;

    void* bar_ptr = nullptr;
    cudaGetSymbolAddress(&bar_ptr, g_bar);
    cudaMemsetAsync(bar_ptr, 0, SS * sizeof(unsigned));

    const int smemBytes = 16384 * 4 + 16 * 256 * 8;   // 64 KB + 32 KB = 96 KB
    cudaFuncSetAttribute(rnn_persistent,
                         cudaFuncAttributeMaxDynamicSharedMemorySize, smemBytes);

    xproj_kernel<<<dim3(HH / 64, (SS * BB) / 64), 256>>>(x, Wx, bx, out);
    rnn_persistent<<<NB, NTH, smemBytes>>>(Wh, bh, out);

    cudaMemcpyAsync(out + (size_t)SS * BH, out + (size_t)(SS - 1) * BH,
                    (size_t)BH * sizeof(float), cudaMemcpyDeviceToDevice);
}